// round 12
// baseline (speedup 1.0000x reference)
#include <cuda_runtime.h>
#include <cuda_bf16.h>
#include <cstdint>

// ROI Align (torchvision semantics), OUT 7x7, adaptive grid <= 4x4.
// features: [B=4, C=256, H=200, W=272] fp32 NCHW
// rois:     [N=512, 5] (b, x1, y1, x2, y2) fp32
// out:      [N, C, 7, 7] fp32
//
// R12: R9 winner + per-ROI meta hoisted into a pre-kernel.
//  - pre-kernel (512 blocks x 64 thr) computes per-ROI weights (y-weights
//    pre-scaled by 1/(gh*gw)), premultiplied offsets, and staging scalars
//    into a __device__ L2-resident buffer
//  - main kernel prologue: 56x LDG.128->STS + 1 broadcast LDG.128
//  - compute phase identical to R9 (2-bin warps = ILP; proven fastest)

#define OUT_H 7
#define OUT_W 7
#define NBINS 49
#define MAXG  4
#define C_TILE 8
#define REG   30               // max staged rows
#define WCOLS 36               // staged row pitch in floats (144B)
#define CPITCH 1084            // floats per channel: 30*36 +4 pad; %32==28,
                               // *4 %16==0 (bulk dst align)

#define FEAT_C 256
#define FEAT_H 200
#define FEAT_W 272
#define FEAT_HW (FEAT_H * FEAT_W)

#define N_ROIS 512
#define META_STRIDE 64         // float4s per ROI (28 y + 28 x + 1 scalars + pad)

__device__ float4 g_meta[N_ROIS * META_STRIDE];   // 512 KB, L2-resident

__device__ __forceinline__ uint32_t smem_u32(const void* p) {
    uint32_t a;
    asm("{ .reg .u64 t; cvta.to.shared.u64 t, %1; cvt.u32.u64 %0, t; }"
        : "=r"(a) : "l"(p));
    return a;
}

// ---------------- pre-kernel: per-ROI meta ----------------
__global__ __launch_bounds__(64)
void roi_meta_kernel(const float* __restrict__ rois)
{
    const int n = blockIdx.x;
    const int t = threadIdx.x;
    const int H = FEAT_H, W = FEAT_W;

    const float* r = rois + n * 5;
    const int   bidx  = (int)r[0];
    const float x1    = r[1];
    const float y1    = r[2];
    const float roi_w = fmaxf(r[3] - x1, 1.0f);
    const float roi_h = fmaxf(r[4] - y1, 1.0f);
    const float bin_h = roi_h * (1.0f / OUT_H);
    const float bin_w = roi_w * (1.0f / OUT_W);
    int gh = (int)ceilf(roi_h * (1.0f / OUT_H)); gh = min(max(gh, 1), MAXG);
    int gw = (int)ceilf(roi_w * (1.0f / OUT_W)); gw = min(max(gw, 1), MAXG);

    const int ry0 = min(max((int)floorf(y1), 0), H - 1);
    const int rx0 = min(max((int)floorf(x1), 0), W - 1);
    const int ax0 = min(rx0 & ~3, W - WCOLS);

    const int ymax = min((int)floorf(y1 + roi_h) + 1, H - 1);
    const int rows_used = min(REG, ymax - ry0 + 1);
    const int xmax = min((int)floorf(x1 + roi_w) + 1, W - 1);
    const int cols_f = min(WCOLS, ((xmax - ax0 + 1 + 3) & ~3));
    const int cols_bytes = cols_f * 4;

    float4* rm = g_meta + n * META_STRIDE;

    if (t < 2 * OUT_H * MAXG) {
        const bool isx = (t >= OUT_H * MAXG);
        const int  tt  = isx ? t - OUT_H * MAXG : t;
        const int  p   = tt >> 2;
        const int  gg  = tt & 3;
        const float start = isx ? x1 : y1;
        const float binsz = isx ? bin_w : bin_h;
        const int   gcnt  = isx ? gw : gh;
        const int   size  = isx ? W : H;
        const float pos = start + (float)p * binsz + ((float)gg + 0.5f) * binsz / (float)gcnt;
        const bool valid = (pos >= -1.0f) && (pos <= (float)size);
        float pp = fmaxf(pos, 0.0f);
        int low = min((int)floorf(pp), size - 1);
        if (low >= size - 1) pp = (float)(size - 1);
        const float frac = pp - (float)low;
        const float m = valid ? 1.0f : 0.0f;
        const int hi = min(low + 1, size - 1);
        float4 mv;
        if (isx) {
            mv.x = (1.0f - frac) * m;
            mv.y = frac * m;
            mv.z = __int_as_float(min(max(low - ax0, 0), cols_f - 1));
            mv.w = __int_as_float(min(max(hi  - ax0, 0), cols_f - 1));
            rm[28 + tt] = mv;
        } else {
            const float inv = 1.0f / (float)(gh * gw);   // fold averaging into wy
            mv.x = (1.0f - frac) * m * inv;
            mv.y = frac * m * inv;
            mv.z = __int_as_float(min(max(low - ry0, 0), rows_used - 1) * WCOLS);
            mv.w = __int_as_float(min(max(hi  - ry0, 0), rows_used - 1) * WCOLS);
            rm[tt] = mv;
        }
    } else if (t == 56) {
        int4 s;
        s.x = bidx * (FEAT_C * FEAT_HW) + ry0 * W + ax0;   // element offset
        s.y = rows_used;
        s.z = cols_bytes;
        s.w = (gh << 8) | gw;
        *(int4*)&rm[56] = s;
    }
}

// ---------------- main kernel ----------------
struct __align__(16) SmemLayout {
    float    region[C_TILE * CPITCH];   // [c][row][36]
    float    s_out[C_TILE * NBINS];
    float4   ymeta[OUT_H * MAXG];       // wy0*inv, wy1*inv, rl*36, rh*36
    float4   xmeta[OUT_H * MAXG];       // wx0, wx1, cl, ch
    unsigned long long mbar;
};

// one bin, one channel. x-meta in registers; 8 lanes share tap addrs.
template<int GW>
__device__ __forceinline__ float bin_acc(const float* __restrict__ regc,
                                         const float4* __restrict__ ym,
                                         const float4* __restrict__ xm,
                                         int gh)
{
    float wx0[GW], wx1[GW];
    int   cl[GW],  ch[GW];
    #pragma unroll
    for (int ix = 0; ix < GW; ++ix) {
        const float4 mx = xm[ix];
        wx0[ix] = mx.x;  wx1[ix] = mx.y;
        cl[ix] = __float_as_int(mx.z);
        ch[ix] = __float_as_int(mx.w);
    }
    float acc = 0.0f;
    for (int iy = 0; iy < gh; ++iy) {
        const float4 my = ym[iy];
        const float* rlo = regc + __float_as_int(my.z);
        const float* rhi = regc + __float_as_int(my.w);
        float ra0 = 0.0f, ra1 = 0.0f;
        #pragma unroll
        for (int ix = 0; ix < GW; ++ix) {
            ra0 += wx0[ix] * rlo[cl[ix]] + wx1[ix] * rlo[ch[ix]];
            ra1 += wx0[ix] * rhi[cl[ix]] + wx1[ix] * rhi[ch[ix]];
        }
        acc += my.x * ra0 + my.y * ra1;   // wy already carries 1/(gh*gw)
    }
    return acc;
}

template<int GW>
__device__ __forceinline__ void compute_bins(const SmemLayout& sm, float* s_out,
                                             int tid, int gh)
{
    const int c   = tid & (C_TILE - 1);
    const int grp = tid >> 3;             // 32 bin groups (2-round, R9 ILP)
    const float* regc = sm.region + c * CPITCH;
    #pragma unroll
    for (int bin = grp; bin < NBINS; bin += 32) {
        const int ph = bin / OUT_W;
        const int pw = bin - ph * OUT_W;
        const float4* ym = sm.ymeta + ph * MAXG;
        const float4* xm = sm.xmeta + pw * MAXG;
        s_out[c * NBINS + bin] = bin_acc<GW>(regc, ym, xm, gh);
    }
}

__global__ __launch_bounds__(256)
void roi_align_kernel(const float* __restrict__ feat,
                      float* __restrict__ out)
{
    __shared__ SmemLayout sm;

    const int blk = blockIdx.x;
    const int n   = blk & 511;        // roi index
    const int ct  = blk >> 9;         // channel tile (slice-major for L2 reuse)

    const int tid = threadIdx.x;
    const float4* rm = g_meta + n * META_STRIDE;

    // broadcast scalar load (uniform address -> 1 wavefront, L2-hot)
    const int4 s = *(const int4*)&rm[56];
    const int rows_used  = s.y;
    const int cols_bytes = s.z;
    const int gh = s.w >> 8;
    const int gw = s.w & 255;

    // meta -> SMEM (56 x LDG.128 + STS)
    if (tid < 56) {
        const float4 v = rm[tid];
        if (tid < 28) sm.ymeta[tid] = v;
        else          sm.xmeta[tid - 28] = v;
    }

    const uint32_t mbar = smem_u32(&sm.mbar);
    if (tid == 0) {
        asm volatile("mbarrier.init.shared.b64 [%0], 1;" :: "r"(mbar) : "memory");
        asm volatile("mbarrier.arrive.expect_tx.shared.b64 _, [%0], %1;"
                     :: "r"(mbar), "r"(C_TILE * rows_used * cols_bytes) : "memory");
    }
    __syncthreads();

    // phase 1: enqueue bulk row copies
    {
        const int c   = tid >> 5;         // 0..7
        const int row = tid & 31;         // rows >= rows_used skipped
        if (row < rows_used) {
            const float* src = feat + (size_t)s.x
                + (size_t)(ct * C_TILE + c) * (size_t)FEAT_HW + (size_t)(row * FEAT_W);
            const uint32_t dst = smem_u32(sm.region)
                               + (uint32_t)((c * CPITCH + row * WCOLS) * 4);
            asm volatile(
                "cp.async.bulk.shared::cluster.global.mbarrier::complete_tx::bytes "
                "[%0], [%1], %2, [%3];"
                :: "r"(dst), "l"(src), "r"(cols_bytes), "r"(mbar) : "memory");
        }
    }

    // wait for DMA completion (parity 0: fresh barrier each launch)
    asm volatile(
        "{\n\t"
        ".reg .pred P;\n\t"
        "WAIT_%=:\n\t"
        "mbarrier.try_wait.parity.acquire.cta.shared::cta.b64 P, [%0], 0, 0x989680;\n\t"
        "@P bra DONE_%=;\n\t"
        "bra WAIT_%=;\n\t"
        "DONE_%=:\n\t"
        "}"
        :: "r"(mbar) : "memory");
    __syncthreads();   // also covers meta STS visibility

    // phase 2: R9 mapping, gw-specialized
    switch (gw) {
        case 1:  compute_bins<1>(sm, sm.s_out, tid, gh); break;
        case 2:  compute_bins<2>(sm, sm.s_out, tid, gh); break;
        case 3:  compute_bins<3>(sm, sm.s_out, tid, gh); break;
        default: compute_bins<4>(sm, sm.s_out, tid, gh); break;
    }
    __syncthreads();

    // phase 3: coalesced float4 output write
    {
        float4* ob4 = (float4*)(out + ((size_t)n * FEAT_C + (size_t)ct * C_TILE) * NBINS);
        const float4* so4 = (const float4*)sm.s_out;
        if (tid < (C_TILE * NBINS) / 4)      // 98 threads x 16B
            ob4[tid] = so4[tid];
    }
}

extern "C" void kernel_launch(void* const* d_in, const int* in_sizes, int n_in,
                              void* d_out, int out_size)
{
    const float* feat = (const float*)d_in[0];
    const float* rois = (const float*)d_in[1];
    float* out = (float*)d_out;
    const int N = in_sizes[1] / 5;

    roi_meta_kernel<<<N, 64>>>(rois);
    roi_align_kernel<<<N * (FEAT_C / C_TILE), 256>>>(feat, out);
}

// round 13
// speedup vs baseline: 1.2485x; 1.2485x over previous
#include <cuda_runtime.h>
#include <cuda_bf16.h>
#include <cstdint>

// ROI Align (torchvision semantics), OUT 7x7, adaptive grid <= 4x4.
// features: [B=4, C=256, H=200, W=272] fp32 NCHW
// rois:     [N=512, 5] (b, x1, y1, x2, y2) fp32
// out:      [N, C, 7, 7] fp32
//
// R13: R9 winner with 2 channel-tiles fused per block:
//  - per-ROI decode + weights paid once per 2 tiles (was once per tile)
//  - double-buffered regions + 2 mbarriers; both DMAs enqueued up front,
//    tile1 DMA hidden under tile0 compute (no exposed spin -- R12 lesson)
//  - compute phase byte-for-byte R9 (2-bin warps / gw templates / lane=chan)

#define OUT_H 7
#define OUT_W 7
#define NBINS 49
#define MAXG  4
#define C_TILE 8
#define REG   30               // max staged rows
#define WCOLS 36               // staged row pitch in floats (144B)
#define CPITCH 1084            // floats per channel: 30*36 +4 pad; %32==28,
                               // *4 %16==0 (bulk dst align)

#define FEAT_C 256
#define FEAT_H 200
#define FEAT_W 272
#define FEAT_HW (FEAT_H * FEAT_W)

__device__ __forceinline__ uint32_t smem_u32(const void* p) {
    uint32_t a;
    asm("{ .reg .u64 t; cvta.to.shared.u64 t, %1; cvt.u32.u64 %0, t; }"
        : "=r"(a) : "l"(p));
    return a;
}

struct __align__(16) SmemLayout {
    float    region[2][C_TILE * CPITCH];  // double-buffered [c][row][36]
    float    s_out[2][C_TILE * NBINS];
    float4   ymeta[OUT_H * MAXG];         // wy0, wy1, rl*36, rh*36
    float4   xmeta[OUT_H * MAXG];         // wx0, wx1, cl, ch
    unsigned long long mbar[2];
};
#define SMEM_TOTAL_BYTES ((int)sizeof(SmemLayout))

// one bin, one channel. x-meta in registers; 8 lanes share tap addrs. (R9)
template<int GW>
__device__ __forceinline__ float bin_acc(const float* __restrict__ regc,
                                         const float4* __restrict__ ym,
                                         const float4* __restrict__ xm,
                                         int gh)
{
    float wx0[GW], wx1[GW];
    int   cl[GW],  ch[GW];
    #pragma unroll
    for (int ix = 0; ix < GW; ++ix) {
        const float4 mx = xm[ix];
        wx0[ix] = mx.x;  wx1[ix] = mx.y;
        cl[ix] = __float_as_int(mx.z);
        ch[ix] = __float_as_int(mx.w);
    }
    float acc = 0.0f;
    for (int iy = 0; iy < gh; ++iy) {
        const float4 my = ym[iy];
        const float* rlo = regc + __float_as_int(my.z);
        const float* rhi = regc + __float_as_int(my.w);
        float ra0 = 0.0f, ra1 = 0.0f;
        #pragma unroll
        for (int ix = 0; ix < GW; ++ix) {
            ra0 += wx0[ix] * rlo[cl[ix]] + wx1[ix] * rlo[ch[ix]];
            ra1 += wx0[ix] * rhi[cl[ix]] + wx1[ix] * rhi[ch[ix]];
        }
        acc += my.x * ra0 + my.y * ra1;
    }
    return acc;
}

template<int GW>
__device__ __forceinline__ void compute_bins(const SmemLayout* sm,
                                             const float* __restrict__ region,
                                             float* __restrict__ s_out,
                                             int tid, int gh, float inv)
{
    const int c   = tid & (C_TILE - 1);
    const int grp = tid >> 3;             // 32 bin groups (2-round, R9 ILP)
    const float* regc = region + c * CPITCH;
    #pragma unroll
    for (int bin = grp; bin < NBINS; bin += 32) {
        const int ph = bin / OUT_W;
        const int pw = bin - ph * OUT_W;
        const float4* ym = sm->ymeta + ph * MAXG;
        const float4* xm = sm->xmeta + pw * MAXG;
        s_out[c * NBINS + bin] = bin_acc<GW>(regc, ym, xm, gh) * inv;
    }
}

__device__ __forceinline__ void mbar_wait0(uint32_t mbar) {
    asm volatile(
        "{\n\t"
        ".reg .pred P;\n\t"
        "WAIT_%=:\n\t"
        "mbarrier.try_wait.parity.acquire.cta.shared::cta.b64 P, [%0], 0, 0x989680;\n\t"
        "@P bra DONE_%=;\n\t"
        "bra WAIT_%=;\n\t"
        "DONE_%=:\n\t"
        "}"
        :: "r"(mbar) : "memory");
}

__global__ __launch_bounds__(256)
void roi_align_kernel(const float* __restrict__ feat,
                      const float* __restrict__ rois,
                      float* __restrict__ out)
{
    extern __shared__ char smem_raw[];
    SmemLayout* sm = (SmemLayout*)smem_raw;

    const int H = FEAT_H, W = FEAT_W;
    const int blk = blockIdx.x;
    const int n    = blk & 511;       // roi index
    const int pair = blk >> 9;        // tile pair 0..3 (slice-major, L2 reuse)
    const int ct0  = pair * 2;

    const float* r = rois + n * 5;
    const int   bidx  = (int)r[0];
    const float x1    = r[1];
    const float y1    = r[2];
    const float roi_w = fmaxf(r[3] - x1, 1.0f);
    const float roi_h = fmaxf(r[4] - y1, 1.0f);
    const float bin_h = roi_h * (1.0f / OUT_H);
    const float bin_w = roi_w * (1.0f / OUT_W);
    int gh = (int)ceilf(roi_h * (1.0f / OUT_H)); gh = min(max(gh, 1), MAXG);
    int gw = (int)ceilf(roi_w * (1.0f / OUT_W)); gw = min(max(gw, 1), MAXG);

    const int ry0 = min(max((int)floorf(y1), 0), H - 1);
    const int rx0 = min(max((int)floorf(x1), 0), W - 1);
    const int ax0 = min(rx0 & ~3, W - WCOLS);   // aligned window, in-bounds

    // dynamic staged extent
    const int ymax = min((int)floorf(y1 + roi_h) + 1, H - 1);
    const int rows_used = min(REG, ymax - ry0 + 1);             // >= 1
    const int xmax = min((int)floorf(x1 + roi_w) + 1, W - 1);
    const int cols_f = min(WCOLS, ((xmax - ax0 + 1 + 3) & ~3)); // mult of 4
    const int cols_bytes = cols_f * 4;                          // mult of 16

    const int tid = threadIdx.x;
    const uint32_t mbar0 = smem_u32(&sm->mbar[0]);
    const uint32_t mbar1 = smem_u32(&sm->mbar[1]);

    // ---- init both mbarriers + expect exact byte counts ----
    if (tid == 0) {
        const int bytes = C_TILE * rows_used * cols_bytes;
        asm volatile("mbarrier.init.shared.b64 [%0], 1;" :: "r"(mbar0) : "memory");
        asm volatile("mbarrier.init.shared.b64 [%0], 1;" :: "r"(mbar1) : "memory");
        asm volatile("mbarrier.arrive.expect_tx.shared.b64 _, [%0], %1;"
                     :: "r"(mbar0), "r"(bytes) : "memory");
        asm volatile("mbarrier.arrive.expect_tx.shared.b64 _, [%0], %1;"
                     :: "r"(mbar1), "r"(bytes) : "memory");
    }
    __syncthreads();

    // ---- phase 1: enqueue BOTH tiles' bulk row copies up front ----
    {
        const int c   = tid >> 5;         // 0..7
        const int row = tid & 31;         // rows >= rows_used skipped
        if (row < rows_used) {
            const size_t rowoff = (size_t)(ry0 + row) * W + ax0;
            const float* src0 = feat
                + ((size_t)bidx * FEAT_C + (size_t)(ct0 * C_TILE + c)) * (size_t)FEAT_HW
                + rowoff;
            const uint32_t doff = (uint32_t)((c * CPITCH + row * WCOLS) * 4);
            const uint32_t dst0 = smem_u32(sm->region[0]) + doff;
            const uint32_t dst1 = smem_u32(sm->region[1]) + doff;
            asm volatile(
                "cp.async.bulk.shared::cluster.global.mbarrier::complete_tx::bytes "
                "[%0], [%1], %2, [%3];"
                :: "r"(dst0), "l"(src0), "r"(cols_bytes), "r"(mbar0) : "memory");
            asm volatile(
                "cp.async.bulk.shared::cluster.global.mbarrier::complete_tx::bytes "
                "[%0], [%1], %2, [%3];"
                :: "r"(dst1), "l"(src0 + (size_t)C_TILE * FEAT_HW),
                   "r"(cols_bytes), "r"(mbar1) : "memory");
        }
    }

    // ---- phase 0 (overlaps DMA): weights + premult clamped offsets ----
    if (tid < 2 * OUT_H * MAXG) {
        const bool isx = (tid >= OUT_H * MAXG);
        const int  t   = isx ? tid - OUT_H * MAXG : tid;
        const int  p   = t >> 2;          // output bin index along axis
        const int  gg  = t & 3;           // grid slot
        const float start = isx ? x1 : y1;
        const float binsz = isx ? bin_w : bin_h;
        const int   gcnt  = isx ? gw : gh;
        const int   size  = isx ? W : H;
        const float pos = start + (float)p * binsz + ((float)gg + 0.5f) * binsz / (float)gcnt;
        const bool valid = (pos >= -1.0f) && (pos <= (float)size);
        float pp = fmaxf(pos, 0.0f);
        int low = min((int)floorf(pp), size - 1);
        if (low >= size - 1) pp = (float)(size - 1);
        const float frac = pp - (float)low;
        const float m = valid ? 1.0f : 0.0f;
        const int hi = min(low + 1, size - 1);
        float4 mv;
        mv.x = (1.0f - frac) * m;
        mv.y = frac * m;
        if (isx) {
            mv.z = __int_as_float(min(max(low - ax0, 0), cols_f - 1));
            mv.w = __int_as_float(min(max(hi  - ax0, 0), cols_f - 1));
            sm->xmeta[t] = mv;
        } else {
            mv.z = __int_as_float(min(max(low - ry0, 0), rows_used - 1) * WCOLS);
            mv.w = __int_as_float(min(max(hi  - ry0, 0), rows_used - 1) * WCOLS);
            sm->ymeta[t] = mv;
        }
    }
    __syncthreads();   // meta visible to all before compute

    const float inv = 1.0f / (float)(gh * gw);

    // ---- tile 0: wait (covered by decode/weights) + compute ----
    mbar_wait0(mbar0);
    switch (gw) {
        case 1:  compute_bins<1>(sm, sm->region[0], sm->s_out[0], tid, gh, inv); break;
        case 2:  compute_bins<2>(sm, sm->region[0], sm->s_out[0], tid, gh, inv); break;
        case 3:  compute_bins<3>(sm, sm->region[0], sm->s_out[0], tid, gh, inv); break;
        default: compute_bins<4>(sm, sm->region[0], sm->s_out[0], tid, gh, inv); break;
    }

    // ---- tile 1: wait (hidden under tile 0 compute) + compute ----
    mbar_wait0(mbar1);
    switch (gw) {
        case 1:  compute_bins<1>(sm, sm->region[1], sm->s_out[1], tid, gh, inv); break;
        case 2:  compute_bins<2>(sm, sm->region[1], sm->s_out[1], tid, gh, inv); break;
        case 3:  compute_bins<3>(sm, sm->region[1], sm->s_out[1], tid, gh, inv); break;
        default: compute_bins<4>(sm, sm->region[1], sm->s_out[1], tid, gh, inv); break;
    }
    __syncthreads();

    // ---- phase 3: coalesced float4 output writes (both tiles) ----
    {
        float4* ob4 = (float4*)(out + ((size_t)n * FEAT_C + (size_t)ct0 * C_TILE) * NBINS);
        const float4* so0 = (const float4*)sm->s_out[0];
        const float4* so1 = (const float4*)sm->s_out[1];
        if (tid < (C_TILE * NBINS) / 4) {            // 98 threads x 16B x 2
            ob4[tid] = so0[tid];
            ob4[(C_TILE * NBINS) / 4 + tid] = so1[tid];
        }
    }
}

extern "C" void kernel_launch(void* const* d_in, const int* in_sizes, int n_in,
                              void* d_out, int out_size)
{
    const float* feat = (const float*)d_in[0];
    const float* rois = (const float*)d_in[1];
    float* out = (float*)d_out;
    const int N = in_sizes[1] / 5;

    cudaFuncSetAttribute(roi_align_kernel,
                         cudaFuncAttributeMaxDynamicSharedMemorySize,
                         SMEM_TOTAL_BYTES);
    roi_align_kernel<<<N * (FEAT_C / (2 * C_TILE)), 256, SMEM_TOTAL_BYTES>>>(feat, rois, out);
}

// round 14
// speedup vs baseline: 1.5680x; 1.2559x over previous
#include <cuda_runtime.h>
#include <cuda_bf16.h>
#include <cstdint>

// ROI Align (torchvision semantics), OUT 7x7, adaptive grid <= 4x4.
// features: [B=4, C=256, H=200, W=272] fp32 NCHW
// rois:     [N=512, 5] (b, x1, y1, x2, y2) fp32
// out:      [N, C, 7, 7] fp32
//
// R14: conservative composite on the R9 winner (structure untouched):
//  - direct-STG epilogue (no s_out staging, no final syncthreads/copy)
//  - 1/(gh*gw) folded into y-weights at meta build (56 threads pay it once)
//  - staging/compute identical to R9: dynamic-extent cp.async.bulk rows,
//    lane=channel broadcast LDS, 2-bin ILP mapping, gw-only templates,
//    slice-major block order for L2 reuse.

#define OUT_H 7
#define OUT_W 7
#define NBINS 49
#define MAXG  4
#define C_TILE 8
#define REG   30               // max staged rows
#define WCOLS 36               // staged row pitch in floats (144B)
#define CPITCH 1084            // floats per channel: 30*36 +4 pad; %32==28,
                               // *4 %16==0 (bulk dst align)

#define FEAT_C 256
#define FEAT_H 200
#define FEAT_W 272
#define FEAT_HW (FEAT_H * FEAT_W)

__device__ __forceinline__ uint32_t smem_u32(const void* p) {
    uint32_t a;
    asm("{ .reg .u64 t; cvta.to.shared.u64 t, %1; cvt.u32.u64 %0, t; }"
        : "=r"(a) : "l"(p));
    return a;
}

struct __align__(16) SmemLayout {
    float    region[C_TILE * CPITCH];   // [c][row][36]
    float4   ymeta[OUT_H * MAXG];       // wy0*inv, wy1*inv, rl*36, rh*36
    float4   xmeta[OUT_H * MAXG];       // wx0, wx1, cl, ch
    unsigned long long mbar;
};

// one bin, one channel. x-meta in registers; 8 lanes share tap addrs. (R9)
template<int GW>
__device__ __forceinline__ float bin_acc(const float* __restrict__ regc,
                                         const float4* __restrict__ ym,
                                         const float4* __restrict__ xm,
                                         int gh)
{
    float wx0[GW], wx1[GW];
    int   cl[GW],  ch[GW];
    #pragma unroll
    for (int ix = 0; ix < GW; ++ix) {
        const float4 mx = xm[ix];
        wx0[ix] = mx.x;  wx1[ix] = mx.y;
        cl[ix] = __float_as_int(mx.z);
        ch[ix] = __float_as_int(mx.w);
    }
    float acc = 0.0f;
    for (int iy = 0; iy < gh; ++iy) {
        const float4 my = ym[iy];
        const float* rlo = regc + __float_as_int(my.z);
        const float* rhi = regc + __float_as_int(my.w);
        float ra0 = 0.0f, ra1 = 0.0f;
        #pragma unroll
        for (int ix = 0; ix < GW; ++ix) {
            ra0 += wx0[ix] * rlo[cl[ix]] + wx1[ix] * rlo[ch[ix]];
            ra1 += wx0[ix] * rhi[cl[ix]] + wx1[ix] * rhi[ch[ix]];
        }
        acc += my.x * ra0 + my.y * ra1;   // wy carries 1/(gh*gw)
    }
    return acc;
}

template<int GW>
__device__ __forceinline__ void compute_bins(const SmemLayout& sm,
                                             float* __restrict__ obase,
                                             int tid, int gh)
{
    const int c   = tid & (C_TILE - 1);
    const int grp = tid >> 3;             // 32 bin groups (2-round, R9 ILP)
    const float* regc = sm.region + c * CPITCH;
    #pragma unroll
    for (int bin = grp; bin < NBINS; bin += 32) {
        const int ph = bin / OUT_W;
        const int pw = bin - ph * OUT_W;
        const float4* ym = sm.ymeta + ph * MAXG;
        const float4* xm = sm.xmeta + pw * MAXG;
        obase[c * NBINS + bin] = bin_acc<GW>(regc, ym, xm, gh);   // direct STG
    }
}

__global__ __launch_bounds__(256)
void roi_align_kernel(const float* __restrict__ feat,
                      const float* __restrict__ rois,
                      float* __restrict__ out)
{
    __shared__ SmemLayout sm;

    const int H = FEAT_H, W = FEAT_W;
    const int blk = blockIdx.x;
    const int n   = blk & 511;        // roi index
    const int ct  = blk >> 9;         // channel tile (slice-major for L2 reuse)

    const float* r = rois + n * 5;
    const int   bidx  = (int)r[0];
    const float x1    = r[1];
    const float y1    = r[2];
    const float roi_w = fmaxf(r[3] - x1, 1.0f);
    const float roi_h = fmaxf(r[4] - y1, 1.0f);
    const float bin_h = roi_h * (1.0f / OUT_H);
    const float bin_w = roi_w * (1.0f / OUT_W);
    int gh = (int)ceilf(roi_h * (1.0f / OUT_H)); gh = min(max(gh, 1), MAXG);
    int gw = (int)ceilf(roi_w * (1.0f / OUT_W)); gw = min(max(gw, 1), MAXG);

    const int ry0 = min(max((int)floorf(y1), 0), H - 1);
    const int rx0 = min(max((int)floorf(x1), 0), W - 1);
    const int ax0 = min(rx0 & ~3, W - WCOLS);   // aligned window, in-bounds

    // dynamic staged extent
    const int ymax = min((int)floorf(y1 + roi_h) + 1, H - 1);
    const int rows_used = min(REG, ymax - ry0 + 1);             // >= 1
    const int xmax = min((int)floorf(x1 + roi_w) + 1, W - 1);
    const int cols_f = min(WCOLS, ((xmax - ax0 + 1 + 3) & ~3)); // mult of 4
    const int cols_bytes = cols_f * 4;                          // mult of 16

    const int tid = threadIdx.x;
    const uint32_t mbar = smem_u32(&sm.mbar);

    // ---- init mbarrier + expect exact staging byte count ----
    if (tid == 0) {
        asm volatile("mbarrier.init.shared.b64 [%0], 1;" :: "r"(mbar) : "memory");
        asm volatile("mbarrier.arrive.expect_tx.shared.b64 _, [%0], %1;"
                     :: "r"(mbar), "r"(C_TILE * rows_used * cols_bytes) : "memory");
    }
    __syncthreads();

    // ---- phase 1: enqueue bulk row copies (shift/mask mapping) ----
    {
        const int c   = tid >> 5;         // 0..7
        const int row = tid & 31;         // rows >= rows_used skipped
        if (row < rows_used) {
            const float* src = feat
                + ((size_t)bidx * FEAT_C + (size_t)(ct * C_TILE + c)) * (size_t)FEAT_HW
                + (size_t)(ry0 + row) * W + ax0;
            const uint32_t dst = smem_u32(sm.region)
                               + (uint32_t)((c * CPITCH + row * WCOLS) * 4);
            asm volatile(
                "cp.async.bulk.shared::cluster.global.mbarrier::complete_tx::bytes "
                "[%0], [%1], %2, [%3];"
                :: "r"(dst), "l"(src), "r"(cols_bytes), "r"(mbar) : "memory");
        }
    }

    // ---- phase 0 (overlaps DMA): weights + premult clamped offsets ----
    if (tid < 2 * OUT_H * MAXG) {
        const bool isx = (tid >= OUT_H * MAXG);
        const int  t   = isx ? tid - OUT_H * MAXG : tid;
        const int  p   = t >> 2;          // output bin index along axis
        const int  gg  = t & 3;           // grid slot
        const float start = isx ? x1 : y1;
        const float binsz = isx ? bin_w : bin_h;
        const int   gcnt  = isx ? gw : gh;
        const int   size  = isx ? W : H;
        const float pos = start + (float)p * binsz + ((float)gg + 0.5f) * binsz / (float)gcnt;
        const bool valid = (pos >= -1.0f) && (pos <= (float)size);
        float pp = fmaxf(pos, 0.0f);
        int low = min((int)floorf(pp), size - 1);
        if (low >= size - 1) pp = (float)(size - 1);
        const float frac = pp - (float)low;
        const float m = valid ? 1.0f : 0.0f;
        const int hi = min(low + 1, size - 1);
        float4 mv;
        if (isx) {
            mv.x = (1.0f - frac) * m;
            mv.y = frac * m;
            mv.z = __int_as_float(min(max(low - ax0, 0), cols_f - 1));
            mv.w = __int_as_float(min(max(hi  - ax0, 0), cols_f - 1));
            sm.xmeta[t] = mv;
        } else {
            const float inv = 1.0f / (float)(gh * gw);   // folded averaging
            mv.x = (1.0f - frac) * m * inv;
            mv.y = frac * m * inv;
            mv.z = __int_as_float(min(max(low - ry0, 0), rows_used - 1) * WCOLS);
            mv.w = __int_as_float(min(max(hi  - ry0, 0), rows_used - 1) * WCOLS);
            sm.ymeta[t] = mv;
        }
    }

    // ---- wait for DMA completion (parity 0: fresh barrier each launch) ----
    asm volatile(
        "{\n\t"
        ".reg .pred P;\n\t"
        "WAIT_%=:\n\t"
        "mbarrier.try_wait.parity.acquire.cta.shared::cta.b64 P, [%0], 0, 0x989680;\n\t"
        "@P bra DONE_%=;\n\t"
        "bra WAIT_%=;\n\t"
        "DONE_%=:\n\t"
        "}"
        :: "r"(mbar) : "memory");
    __syncthreads();   // also covers meta STS visibility

    // ---- phase 2: R9 mapping, gw-specialized, direct STG to out ----
    {
        float* obase = out + ((size_t)n * FEAT_C + (size_t)ct * C_TILE) * NBINS;
        switch (gw) {
            case 1:  compute_bins<1>(sm, obase, tid, gh); break;
            case 2:  compute_bins<2>(sm, obase, tid, gh); break;
            case 3:  compute_bins<3>(sm, obase, tid, gh); break;
            default: compute_bins<4>(sm, obase, tid, gh); break;
        }
    }
}

extern "C" void kernel_launch(void* const* d_in, const int* in_sizes, int n_in,
                              void* d_out, int out_size)
{
    const float* feat = (const float*)d_in[0];
    const float* rois = (const float*)d_in[1];
    float* out = (float*)d_out;
    const int N = in_sizes[1] / 5;

    roi_align_kernel<<<N * (FEAT_C / C_TILE), 256>>>(feat, rois, out);
}

// round 15
// speedup vs baseline: 1.6140x; 1.0293x over previous
#include <cuda_runtime.h>
#include <cuda_bf16.h>
#include <cstdint>

// ROI Align (torchvision semantics), OUT 7x7, adaptive grid <= 4x4.
// features: [B=4, C=256, H=200, W=272] fp32 NCHW
// rois:     [N=512, 5] (b, x1, y1, x2, y2) fp32
// out:      [N, C, 7, 7] fp32
//
// R15: R14 winner + packed f32x2 (FFMA2) tap math:
//  - (rlo, rhi) tap values packed to 64-bit, 2x FFMA2 per tap (was 6 FFMA)
//  - packed y-accumulator, one FFMA2 per iy; unpack+add once per bin
//  - x-weights pre-duplicated into packed regs per bin
//  - launch_bounds(256, 6) to hold regs <= 42 (keep 6 CTAs/SM)
//  - everything else identical to R14 (direct STG, folded inv, dynamic-extent
//    bulk DMA, lane=channel mapping, 2-bin ILP, gw templates, slice-major)

#define OUT_H 7
#define OUT_W 7
#define NBINS 49
#define MAXG  4
#define C_TILE 8
#define REG   30               // max staged rows
#define WCOLS 36               // staged row pitch in floats (144B)
#define CPITCH 1084            // floats per channel: 30*36 +4 pad; %32==28,
                               // *4 %16==0 (bulk dst align)

#define FEAT_C 256
#define FEAT_H 200
#define FEAT_W 272
#define FEAT_HW (FEAT_H * FEAT_W)

__device__ __forceinline__ uint32_t smem_u32(const void* p) {
    uint32_t a;
    asm("{ .reg .u64 t; cvta.to.shared.u64 t, %1; cvt.u32.u64 %0, t; }"
        : "=r"(a) : "l"(p));
    return a;
}

__device__ __forceinline__ uint64_t pack2(float lo, float hi) {
    uint64_t r;
    asm("mov.b64 %0, {%1, %2};" : "=l"(r) : "f"(lo), "f"(hi));
    return r;
}

__device__ __forceinline__ void ffma2(uint64_t& d, uint64_t a, uint64_t b) {
    asm("fma.rn.f32x2 %0, %1, %2, %0;" : "+l"(d) : "l"(a), "l"(b));
}

struct __align__(16) SmemLayout {
    float    region[C_TILE * CPITCH];   // [c][row][36]
    float4   ymeta[OUT_H * MAXG];       // wy0*inv, wy1*inv, rl*36, rh*36
    float4   xmeta[OUT_H * MAXG];       // wx0, wx1, cl, ch
    unsigned long long mbar;
};

// one bin, one channel. x-meta in packed registers; FFMA2 tap math.
template<int GW>
__device__ __forceinline__ float bin_acc(const float* __restrict__ regc,
                                         const float4* __restrict__ ym,
                                         const float4* __restrict__ xm,
                                         int gh)
{
    uint64_t wx0d[GW], wx1d[GW];
    int      cl[GW],  ch[GW];
    #pragma unroll
    for (int ix = 0; ix < GW; ++ix) {
        const float4 mx = xm[ix];
        wx0d[ix] = pack2(mx.x, mx.x);
        wx1d[ix] = pack2(mx.y, mx.y);
        cl[ix] = __float_as_int(mx.z);
        ch[ix] = __float_as_int(mx.w);
    }
    uint64_t accT = 0;                   // (sum wy0*ra0, sum wy1*ra1)
    for (int iy = 0; iy < gh; ++iy) {
        const float4 my = ym[iy];
        const float* rlo = regc + __float_as_int(my.z);
        const float* rhi = regc + __float_as_int(my.w);
        const uint64_t myd = pack2(my.x, my.y);
        uint64_t acc2 = 0;               // (ra0, ra1)
        #pragma unroll
        for (int ix = 0; ix < GW; ++ix) {
            const uint64_t v0 = pack2(rlo[cl[ix]], rhi[cl[ix]]);
            const uint64_t v1 = pack2(rlo[ch[ix]], rhi[ch[ix]]);
            ffma2(acc2, wx0d[ix], v0);
            ffma2(acc2, wx1d[ix], v1);
        }
        ffma2(accT, myd, acc2);
    }
    float lo, hi;
    asm("mov.b64 {%0, %1}, %2;" : "=f"(lo), "=f"(hi) : "l"(accT));
    return lo + hi;                      // wy carries 1/(gh*gw)
}

template<int GW>
__device__ __forceinline__ void compute_bins(const SmemLayout& sm,
                                             float* __restrict__ obase,
                                             int tid, int gh)
{
    const int c   = tid & (C_TILE - 1);
    const int grp = tid >> 3;             // 32 bin groups (2-round, R9 ILP)
    const float* regc = sm.region + c * CPITCH;
    #pragma unroll
    for (int bin = grp; bin < NBINS; bin += 32) {
        const int ph = bin / OUT_W;
        const int pw = bin - ph * OUT_W;
        const float4* ym = sm.ymeta + ph * MAXG;
        const float4* xm = sm.xmeta + pw * MAXG;
        obase[c * NBINS + bin] = bin_acc<GW>(regc, ym, xm, gh);   // direct STG
    }
}

__global__ __launch_bounds__(256, 6)
void roi_align_kernel(const float* __restrict__ feat,
                      const float* __restrict__ rois,
                      float* __restrict__ out)
{
    __shared__ SmemLayout sm;

    const int H = FEAT_H, W = FEAT_W;
    const int blk = blockIdx.x;
    const int n   = blk & 511;        // roi index
    const int ct  = blk >> 9;         // channel tile (slice-major for L2 reuse)

    const float* r = rois + n * 5;
    const int   bidx  = (int)r[0];
    const float x1    = r[1];
    const float y1    = r[2];
    const float roi_w = fmaxf(r[3] - x1, 1.0f);
    const float roi_h = fmaxf(r[4] - y1, 1.0f);
    const float bin_h = roi_h * (1.0f / OUT_H);
    const float bin_w = roi_w * (1.0f / OUT_W);
    int gh = (int)ceilf(roi_h * (1.0f / OUT_H)); gh = min(max(gh, 1), MAXG);
    int gw = (int)ceilf(roi_w * (1.0f / OUT_W)); gw = min(max(gw, 1), MAXG);

    const int ry0 = min(max((int)floorf(y1), 0), H - 1);
    const int rx0 = min(max((int)floorf(x1), 0), W - 1);
    const int ax0 = min(rx0 & ~3, W - WCOLS);   // aligned window, in-bounds

    // dynamic staged extent
    const int ymax = min((int)floorf(y1 + roi_h) + 1, H - 1);
    const int rows_used = min(REG, ymax - ry0 + 1);             // >= 1
    const int xmax = min((int)floorf(x1 + roi_w) + 1, W - 1);
    const int cols_f = min(WCOLS, ((xmax - ax0 + 1 + 3) & ~3)); // mult of 4
    const int cols_bytes = cols_f * 4;                          // mult of 16

    const int tid = threadIdx.x;
    const uint32_t mbar = smem_u32(&sm.mbar);

    // ---- init mbarrier + expect exact staging byte count ----
    if (tid == 0) {
        asm volatile("mbarrier.init.shared.b64 [%0], 1;" :: "r"(mbar) : "memory");
        asm volatile("mbarrier.arrive.expect_tx.shared.b64 _, [%0], %1;"
                     :: "r"(mbar), "r"(C_TILE * rows_used * cols_bytes) : "memory");
    }
    __syncthreads();

    // ---- phase 1: enqueue bulk row copies (shift/mask mapping) ----
    {
        const int c   = tid >> 5;         // 0..7
        const int row = tid & 31;         // rows >= rows_used skipped
        if (row < rows_used) {
            const float* src = feat
                + ((size_t)bidx * FEAT_C + (size_t)(ct * C_TILE + c)) * (size_t)FEAT_HW
                + (size_t)(ry0 + row) * W + ax0;
            const uint32_t dst = smem_u32(sm.region)
                               + (uint32_t)((c * CPITCH + row * WCOLS) * 4);
            asm volatile(
                "cp.async.bulk.shared::cluster.global.mbarrier::complete_tx::bytes "
                "[%0], [%1], %2, [%3];"
                :: "r"(dst), "l"(src), "r"(cols_bytes), "r"(mbar) : "memory");
        }
    }

    // ---- phase 0 (overlaps DMA): weights + premult clamped offsets ----
    if (tid < 2 * OUT_H * MAXG) {
        const bool isx = (tid >= OUT_H * MAXG);
        const int  t   = isx ? tid - OUT_H * MAXG : tid;
        const int  p   = t >> 2;          // output bin index along axis
        const int  gg  = t & 3;           // grid slot
        const float start = isx ? x1 : y1;
        const float binsz = isx ? bin_w : bin_h;
        const int   gcnt  = isx ? gw : gh;
        const int   size  = isx ? W : H;
        const float pos = start + (float)p * binsz + ((float)gg + 0.5f) * binsz / (float)gcnt;
        const bool valid = (pos >= -1.0f) && (pos <= (float)size);
        float pp = fmaxf(pos, 0.0f);
        int low = min((int)floorf(pp), size - 1);
        if (low >= size - 1) pp = (float)(size - 1);
        const float frac = pp - (float)low;
        const float m = valid ? 1.0f : 0.0f;
        const int hi = min(low + 1, size - 1);
        float4 mv;
        if (isx) {
            mv.x = (1.0f - frac) * m;
            mv.y = frac * m;
            mv.z = __int_as_float(min(max(low - ax0, 0), cols_f - 1));
            mv.w = __int_as_float(min(max(hi  - ax0, 0), cols_f - 1));
            sm.xmeta[t] = mv;
        } else {
            const float inv = 1.0f / (float)(gh * gw);   // folded averaging
            mv.x = (1.0f - frac) * m * inv;
            mv.y = frac * m * inv;
            mv.z = __int_as_float(min(max(low - ry0, 0), rows_used - 1) * WCOLS);
            mv.w = __int_as_float(min(max(hi  - ry0, 0), rows_used - 1) * WCOLS);
            sm.ymeta[t] = mv;
        }
    }

    // ---- wait for DMA completion (parity 0: fresh barrier each launch) ----
    asm volatile(
        "{\n\t"
        ".reg .pred P;\n\t"
        "WAIT_%=:\n\t"
        "mbarrier.try_wait.parity.acquire.cta.shared::cta.b64 P, [%0], 0, 0x989680;\n\t"
        "@P bra DONE_%=;\n\t"
        "bra WAIT_%=;\n\t"
        "DONE_%=:\n\t"
        "}"
        :: "r"(mbar) : "memory");
    __syncthreads();   // also covers meta STS visibility

    // ---- phase 2: R9 mapping, gw-specialized, FFMA2 taps, direct STG ----
    {
        float* obase = out + ((size_t)n * FEAT_C + (size_t)ct * C_TILE) * NBINS;
        switch (gw) {
            case 1:  compute_bins<1>(sm, obase, tid, gh); break;
            case 2:  compute_bins<2>(sm, obase, tid, gh); break;
            case 3:  compute_bins<3>(sm, obase, tid, gh); break;
            default: compute_bins<4>(sm, obase, tid, gh); break;
        }
    }
}

extern "C" void kernel_launch(void* const* d_in, const int* in_sizes, int n_in,
                              void* d_out, int out_size)
{
    const float* feat = (const float*)d_in[0];
    const float* rois = (const float*)d_in[1];
    float* out = (float*)d_out;
    const int N = in_sizes[1] / 5;

    roi_align_kernel<<<N * (FEAT_C / C_TILE), 256>>>(feat, rois, out);
}

// round 17
// speedup vs baseline: 1.6460x; 1.0198x over previous
#include <cuda_runtime.h>
#include <cuda_bf16.h>
#include <cstdint>

// ROI Align (torchvision semantics), OUT 7x7, adaptive grid <= 4x4.
// features: [B=4, C=256, H=200, W=272] fp32 NCHW
// rois:     [N=512, 5] (b, x1, y1, x2, y2) fp32
// out:      [N, C, 7, 7] fp32
//
// R16: R15 winner + split-wait DMA overlap:
//  - two mbarriers: mbar0 covers staged rows [0, r_split) (all rows the
//    first bin of every thread can touch, ph<=4 bound + fp margin),
//    mbar1 covers the rest
//  - compute bin1 after mbar0 only -> first-bin compute overlaps the tail
//    of the DMA completion spread; bin2 (grp<=16) waits mbar1
//  - everything else identical to R15 (FFMA2 taps, direct STG, folded inv,
//    dynamic-extent bulk DMA, lane=channel mapping, gw templates)

#define OUT_H 7
#define OUT_W 7
#define NBINS 49
#define MAXG  4
#define C_TILE 8
#define REG   30               // max staged rows
#define WCOLS 36               // staged row pitch in floats (144B)
#define CPITCH 1084            // floats per channel: 30*36 +4 pad; %32==28,
                               // *4 %16==0 (bulk dst align)

#define FEAT_C 256
#define FEAT_H 200
#define FEAT_W 272
#define FEAT_HW (FEAT_H * FEAT_W)

__device__ __forceinline__ uint32_t smem_u32(const void* p) {
    uint32_t a;
    asm("{ .reg .u64 t; cvta.to.shared.u64 t, %1; cvt.u32.u64 %0, t; }"
        : "=r"(a) : "l"(p));
    return a;
}

__device__ __forceinline__ uint64_t pack2(float lo, float hi) {
    uint64_t r;
    asm("mov.b64 %0, {%1, %2};" : "=l"(r) : "f"(lo), "f"(hi));
    return r;
}

__device__ __forceinline__ void ffma2(uint64_t& d, uint64_t a, uint64_t b) {
    asm("fma.rn.f32x2 %0, %1, %2, %0;" : "+l"(d) : "l"(a), "l"(b));
}

__device__ __forceinline__ void mbar_wait0(uint32_t mbar) {
    asm volatile(
        "{\n\t"
        ".reg .pred P;\n\t"
        "WAIT_%=:\n\t"
        "mbarrier.try_wait.parity.acquire.cta.shared::cta.b64 P, [%0], 0, 0x989680;\n\t"
        "@P bra DONE_%=;\n\t"
        "bra WAIT_%=;\n\t"
        "DONE_%=:\n\t"
        "}"
        :: "r"(mbar) : "memory");
}

struct __align__(16) SmemLayout {
    float    region[C_TILE * CPITCH];   // [c][row][36]
    float4   ymeta[OUT_H * MAXG];       // wy0*inv, wy1*inv, rl*36, rh*36
    float4   xmeta[OUT_H * MAXG];       // wx0, wx1, cl, ch
    unsigned long long mbar[2];
};

// one bin, one channel. x-meta in packed registers; FFMA2 tap math. (R15)
template<int GW>
__device__ __forceinline__ float bin_acc(const float* __restrict__ regc,
                                         const float4* __restrict__ ym,
                                         const float4* __restrict__ xm,
                                         int gh)
{
    uint64_t wx0d[GW], wx1d[GW];
    int      cl[GW],  ch[GW];
    #pragma unroll
    for (int ix = 0; ix < GW; ++ix) {
        const float4 mx = xm[ix];
        wx0d[ix] = pack2(mx.x, mx.x);
        wx1d[ix] = pack2(mx.y, mx.y);
        cl[ix] = __float_as_int(mx.z);
        ch[ix] = __float_as_int(mx.w);
    }
    uint64_t accT = 0;                   // (sum wy0*ra0, sum wy1*ra1)
    for (int iy = 0; iy < gh; ++iy) {
        const float4 my = ym[iy];
        const float* rlo = regc + __float_as_int(my.z);
        const float* rhi = regc + __float_as_int(my.w);
        const uint64_t myd = pack2(my.x, my.y);
        uint64_t acc2 = 0;               // (ra0, ra1)
        #pragma unroll
        for (int ix = 0; ix < GW; ++ix) {
            const uint64_t v0 = pack2(rlo[cl[ix]], rhi[cl[ix]]);
            const uint64_t v1 = pack2(rlo[ch[ix]], rhi[ch[ix]]);
            ffma2(acc2, wx0d[ix], v0);
            ffma2(acc2, wx1d[ix], v1);
        }
        ffma2(accT, myd, acc2);
    }
    float lo, hi;
    asm("mov.b64 {%0, %1}, %2;" : "=f"(lo), "=f"(hi) : "l"(accT));
    return lo + hi;                      // wy carries 1/(gh*gw)
}

template<int GW>
__device__ __forceinline__ float one_bin(const SmemLayout& sm,
                                         const float* __restrict__ regc,
                                         int bin, int gh)
{
    const int ph = bin / OUT_W;
    const int pw = bin - ph * OUT_W;
    const float4* ym = sm.ymeta + ph * MAXG;
    const float4* xm = sm.xmeta + pw * MAXG;
    return bin_acc<GW>(regc, ym, xm, gh);
}

template<int GW>
__device__ __forceinline__ void compute_split(const SmemLayout& sm,
                                              float* __restrict__ obase,
                                              int tid, int gh,
                                              uint32_t mbar0, uint32_t mbar1)
{
    const int c   = tid & (C_TILE - 1);
    const int grp = tid >> 3;             // first bin: grp (ph <= 4)
    const float* regc = sm.region + c * CPITCH;

    mbar_wait0(mbar0);                    // rows for ph<=4 are resident
    obase[c * NBINS + grp] = one_bin<GW>(sm, regc, grp, gh);

    const int bin2 = grp + 32;            // ph >= 4: needs full tile
    if (bin2 < NBINS) {
        mbar_wait0(mbar1);
        obase[c * NBINS + bin2] = one_bin<GW>(sm, regc, bin2, gh);
    }
}

__global__ __launch_bounds__(256, 6)
void roi_align_kernel(const float* __restrict__ feat,
                      const float* __restrict__ rois,
                      float* __restrict__ out)
{
    __shared__ SmemLayout sm;

    const int H = FEAT_H, W = FEAT_W;
    const int blk = blockIdx.x;
    const int n   = blk & 511;        // roi index
    const int ct  = blk >> 9;         // channel tile (slice-major for L2 reuse)

    const float* r = rois + n * 5;
    const int   bidx  = (int)r[0];
    const float x1    = r[1];
    const float y1    = r[2];
    const float roi_w = fmaxf(r[3] - x1, 1.0f);
    const float roi_h = fmaxf(r[4] - y1, 1.0f);
    const float bin_h = roi_h * (1.0f / OUT_H);
    const float bin_w = roi_w * (1.0f / OUT_W);
    int gh = (int)ceilf(roi_h * (1.0f / OUT_H)); gh = min(max(gh, 1), MAXG);
    int gw = (int)ceilf(roi_w * (1.0f / OUT_W)); gw = min(max(gw, 1), MAXG);

    const int ry0 = min(max((int)floorf(y1), 0), H - 1);
    const int rx0 = min(max((int)floorf(x1), 0), W - 1);
    const int ax0 = min(rx0 & ~3, W - WCOLS);   // aligned window, in-bounds

    // dynamic staged extent
    const int ymax = min((int)floorf(y1 + roi_h) + 1, H - 1);
    const int rows_used = min(REG, ymax - ry0 + 1);             // >= 1
    const int xmax = min((int)floorf(x1 + roi_w) + 1, W - 1);
    const int cols_f = min(WCOLS, ((xmax - ax0 + 1 + 3) & ~3)); // mult of 4
    const int cols_bytes = cols_f * 4;                          // mult of 16

    // split row: covers every row any ph<=4 tap can reference (+fp margin)
    const int r_split = min(rows_used,
                            max(1, (int)floorf(y1 + 5.0f * bin_h) - ry0 + 3));

    const int tid = threadIdx.x;
    const uint32_t mbar0 = smem_u32(&sm.mbar[0]);
    const uint32_t mbar1 = smem_u32(&sm.mbar[1]);

    // ---- init both mbarriers + expect exact byte counts per half ----
    if (tid == 0) {
        asm volatile("mbarrier.init.shared.b64 [%0], 1;" :: "r"(mbar0) : "memory");
        asm volatile("mbarrier.init.shared.b64 [%0], 1;" :: "r"(mbar1) : "memory");
        asm volatile("mbarrier.arrive.expect_tx.shared.b64 _, [%0], %1;"
                     :: "r"(mbar0), "r"(C_TILE * r_split * cols_bytes) : "memory");
        asm volatile("mbarrier.arrive.expect_tx.shared.b64 _, [%0], %1;"
                     :: "r"(mbar1),
                        "r"(C_TILE * (rows_used - r_split) * cols_bytes) : "memory");
    }
    __syncthreads();

    // ---- phase 1: enqueue bulk row copies, routed to the right mbar ----
    {
        const int c   = tid >> 5;         // 0..7
        const int row = tid & 31;         // rows >= rows_used skipped
        if (row < rows_used) {
            const uint32_t mb = (row < r_split) ? mbar0 : mbar1;
            const float* src = feat
                + ((size_t)bidx * FEAT_C + (size_t)(ct * C_TILE + c)) * (size_t)FEAT_HW
                + (size_t)(ry0 + row) * W + ax0;
            const uint32_t dst = smem_u32(sm.region)
                               + (uint32_t)((c * CPITCH + row * WCOLS) * 4);
            asm volatile(
                "cp.async.bulk.shared::cluster.global.mbarrier::complete_tx::bytes "
                "[%0], [%1], %2, [%3];"
                :: "r"(dst), "l"(src), "r"(cols_bytes), "r"(mb) : "memory");
        }
    }

    // ---- phase 0 (overlaps DMA): weights + premult clamped offsets ----
    if (tid < 2 * OUT_H * MAXG) {
        const bool isx = (tid >= OUT_H * MAXG);
        const int  t   = isx ? tid - OUT_H * MAXG : tid;
        const int  p   = t >> 2;          // output bin index along axis
        const int  gg  = t & 3;           // grid slot
        const float start = isx ? x1 : y1;
        const float binsz = isx ? bin_w : bin_h;
        const int   gcnt  = isx ? gw : gh;
        const int   size  = isx ? W : H;
        const float pos = start + (float)p * binsz + ((float)gg + 0.5f) * binsz / (float)gcnt;
        const bool valid = (pos >= -1.0f) && (pos <= (float)size);
        float pp = fmaxf(pos, 0.0f);
        int low = min((int)floorf(pp), size - 1);
        if (low >= size - 1) pp = (float)(size - 1);
        const float frac = pp - (float)low;
        const float m = valid ? 1.0f : 0.0f;
        const int hi = min(low + 1, size - 1);
        float4 mv;
        if (isx) {
            mv.x = (1.0f - frac) * m;
            mv.y = frac * m;
            mv.z = __int_as_float(min(max(low - ax0, 0), cols_f - 1));
            mv.w = __int_as_float(min(max(hi  - ax0, 0), cols_f - 1));
            sm.xmeta[t] = mv;
        } else {
            const float inv = 1.0f / (float)(gh * gw);   // folded averaging
            mv.x = (1.0f - frac) * m * inv;
            mv.y = frac * m * inv;
            mv.z = __int_as_float(min(max(low - ry0, 0), rows_used - 1) * WCOLS);
            mv.w = __int_as_float(min(max(hi  - ry0, 0), rows_used - 1) * WCOLS);
            sm.ymeta[t] = mv;
        }
    }
    __syncthreads();   // meta visible; DMA still possibly in flight

    // ---- phase 2: split-wait compute, gw-specialized, direct STG ----
    {
        float* obase = out + ((size_t)n * FEAT_C + (size_t)ct * C_TILE) * NBINS;
        switch (gw) {
            case 1:  compute_split<1>(sm, obase, tid, gh, mbar0, mbar1); break;
            case 2:  compute_split<2>(sm, obase, tid, gh, mbar0, mbar1); break;
            case 3:  compute_split<3>(sm, obase, tid, gh, mbar0, mbar1); break;
            default: compute_split<4>(sm, obase, tid, gh, mbar0, mbar1); break;
        }
    }
}

extern "C" void kernel_launch(void* const* d_in, const int* in_sizes, int n_in,
                              void* d_out, int out_size)
{
    const float* feat = (const float*)d_in[0];
    const float* rois = (const float*)d_in[1];
    float* out = (float*)d_out;
    const int N = in_sizes[1] / 5;

    roi_align_kernel<<<N * (FEAT_C / C_TILE), 256>>>(feat, rois, out);
}